// round 14
// baseline (speedup 1.0000x reference)
#include <cuda_runtime.h>

#define NOBJ   4096
#define DIM    1024
#define DIM2   2048
#define NREL   8
#define NPAIR  65536

// Scratch (device globals — no allocation allowed)
__device__ float g_M[NREL * DIM2];   // fused weight M = W2 @ W1, 64 KB
__device__ float g_c[NREL];          // fused bias c = W2@b1 + b2
__device__ float g_U[NOBJ * 16];     // per-object projections, 256 KB
                                     //   [o][0:8]  = feats[o]·M[:, :1024]ᵀ
                                     //   [o][8:16] = feats[o]·M[:, 1024:]ᵀ + c

// Packed fp32x2 FMA: d = a*b + d elementwise on (lo,hi) pairs.
__device__ __forceinline__ void ffma2(unsigned long long& acc,
                                      unsigned long long a,
                                      unsigned long long b) {
    asm("fma.rn.f32x2 %0, %1, %2, %0;" : "+l"(acc) : "l"(a), "l"(b));
}

// ---------------------------------------------------------------------------
// M[r][j] = sum_i W2[r][i] * W1[i][j]  (+ block 0 computes c = W2·b1 + b2)
// Grid 128 x 256 — exact R4/R12 body. NO grid-dependency sync: reads only
// harness inputs, writes g_M/g_c which the preceding kernel in the stream
// (gather of the previous graph replay) never touches, so under PDL this
// kernel overlaps the previous replay's gather drain.
// ---------------------------------------------------------------------------
__global__ void __launch_bounds__(256) m_kernel(const float* __restrict__ W1,
                                                const float* __restrict__ W2,
                                                const float* __restrict__ b1,
                                                const float* __restrict__ b2) {
    __shared__ float sW2[NREL][DIM];       // 32 KB
    __shared__ float sAcc[16][NREL][16];   // 8 KB  [ichunk][r][jloc]
    const int tx = threadIdx.x;

    const float4* __restrict__ W24 = (const float4*)W2;
    float4* sW24 = (float4*)&sW2[0][0];
    for (int i = tx; i < (NREL * DIM) / 4; i += 256) sW24[i] = W24[i];
    __syncthreads();

    const int jloc  = tx & 15;
    const int ic    = tx >> 4;                 // 0..15
    const int j     = blockIdx.x * 16 + jloc;
    const int ibase = ic * 64;

    float acc[NREL];
#pragma unroll
    for (int r = 0; r < NREL; r++) acc[r] = 0.f;

#pragma unroll 8
    for (int ii = 0; ii < 64; ii++) {
        const int i = ibase + ii;
        float w1 = __ldg(&W1[i * DIM2 + j]);
#pragma unroll
        for (int r = 0; r < NREL; r++) acc[r] += sW2[r][i] * w1;
    }
#pragma unroll
    for (int r = 0; r < NREL; r++) sAcc[ic][r][jloc] = acc[r];
    __syncthreads();

    if (tx < 128) {
        const int r = tx >> 4, jl = tx & 15;
        float s = 0.f;
#pragma unroll
        for (int c = 0; c < 16; c++) s += sAcc[c][r][jl];   // fixed order
        g_M[r * DIM2 + blockIdx.x * 16 + jl] = s;
    }

    if (blockIdx.x == 0) {                 // c[r] = W2[r]·b1 + b2[r]
        const int w = tx >> 5, lane = tx & 31;
        float t = 0.f;
        for (int i = lane; i < DIM; i += 32) t += b1[i] * sW2[w][i];
#pragma unroll
        for (int off = 16; off; off >>= 1)
            t += __shfl_xor_sync(0xffffffffu, t, off);
        if (lane == 0) g_c[w] = t + b2[w];
    }
}

// ---------------------------------------------------------------------------
// U table: U[o][j] = feats[o] · Mrow_j   (+ c[j] folded into the object half)
// Exact R12 body + PDL: launches during m_kernel's drain; waits for m before
// touching g_M / g_c. Grid 256 x 256 (2048 warps).
// ---------------------------------------------------------------------------
__global__ void __launch_bounds__(256) u_kernel(const float* __restrict__ feats) {
    const int gw   = (blockIdx.x * 256 + threadIdx.x) >> 5;  // 0..2047
    const int lane = threadIdx.x & 31;
    const int pair = gw >> 1;
    const int half = gw & 1;           // 0: sub cols, 1: obj cols
    const int obase = pair * 4;

    const longlong2* __restrict__ F2 = (const longlong2*)feats;  // 256 per row
    const longlong2* __restrict__ M2 = (const longlong2*)g_M;    // row j at j*512
    const int jbase = half * 256;      // +1024 floats for obj half

    // Prologue done (index math only) — now wait for m_kernel's writes.
    cudaGridDependencySynchronize();

    unsigned long long acc[4][8];
#pragma unroll
    for (int k = 0; k < 4; k++)
#pragma unroll
        for (int j = 0; j < 8; j++) acc[k][j] = 0ull;

#pragma unroll 1
    for (int t = 0; t < 8; t++) {      // 8 x 32 lanes x 4 floats = 1024 d
        const int idx = t * 32 + lane;
        unsigned long long fa[4], fb[4];
#pragma unroll
        for (int k = 0; k < 4; k++) {
            longlong2 fv = __ldg(F2 + (obase + k) * 256 + idx);
            fa[k] = (unsigned long long)fv.x;
            fb[k] = (unsigned long long)fv.y;
        }
#pragma unroll
        for (int j = 0; j < 8; j++) {
            longlong2 mv = __ldg(M2 + j * 512 + jbase + idx);
            const unsigned long long ma = (unsigned long long)mv.x;
            const unsigned long long mb = (unsigned long long)mv.y;
#pragma unroll
            for (int k = 0; k < 4; k++) {
                ffma2(acc[k][j], fa[k], ma);
                ffma2(acc[k][j], fb[k], mb);
            }
        }
    }

    // Collapse packed halves -> 32 scalar partials per lane (vi = k*8+j).
    float v[32];
#pragma unroll
    for (int k = 0; k < 4; k++)
#pragma unroll
        for (int j = 0; j < 8; j++) {
            float2 p = *(float2*)&acc[k][j];
            v[k * 8 + j] = p.x + p.y;
        }

    // Butterfly fold: 5 stages, 31 shfl. Lane L ends with the full sum of
    // original index bitrev5(L) in v[0].
    int nv = 32;
#pragma unroll
    for (int d = 1; d < 32; d <<= 1) {
        nv >>= 1;
        const bool up = (lane & d) != 0;
#pragma unroll
        for (int i = 0; i < 16; i++) {
            if (i < nv) {
                float send = up ? v[i] : v[i + nv];
                float recv = __shfl_xor_sync(0xffffffffu, send, d);
                v[i] = (up ? v[i + nv] : v[i]) + recv;
            }
        }
    }

    const int vi = __brev(lane) >> 27;   // bitrev5
    const int k = vi >> 3;
    const int j = vi & 7;
    const float bias = half ? g_c[j] : 0.f;   // fold c into object half
    g_U[(obase + k) * 16 + half * 8 + j] = v[0] + bias;
}

// ---------------------------------------------------------------------------
// out[p][r] = U[s_p][r] + U[o_p][8+r]   (c already folded into U's obj half)
// PDL: pairs load issues during u_kernel's drain (independent data), then
// sync before reading g_U. 1 pair per thread, grid 256 x 256.
// ---------------------------------------------------------------------------
__global__ void __launch_bounds__(256) gather_kernel(const int* __restrict__ pairs,
                                                     float* __restrict__ out) {
    const int p = blockIdx.x * 256 + threadIdx.x;    // 0..65535
    int2 pr = __ldg(&((const int2*)pairs)[p]);       // independent of u_kernel

    cudaGridDependencySynchronize();                 // now g_U is valid

    const float4* __restrict__ U4 = (const float4*)g_U;
    float4 a0 = __ldg(&U4[pr.x * 4 + 0]);
    float4 a1 = __ldg(&U4[pr.x * 4 + 1]);
    float4 b0 = __ldg(&U4[pr.y * 4 + 2]);
    float4 b1 = __ldg(&U4[pr.y * 4 + 3]);
    float4 r0, r1;
    r0.x = a0.x + b0.x;  r0.y = a0.y + b0.y;
    r0.z = a0.z + b0.z;  r0.w = a0.w + b0.w;
    r1.x = a1.x + b1.x;  r1.y = a1.y + b1.y;
    r1.z = a1.z + b1.z;  r1.w = a1.w + b1.w;
    float4* __restrict__ O4 = (float4*)out;
    O4[p * 2 + 0] = r0;
    O4[p * 2 + 1] = r1;
}

extern "C" void kernel_launch(void* const* d_in, const int* in_sizes, int n_in,
                              void* d_out, int out_size) {
    const float* feats = (const float*)d_in[0];   // (4096, 1024) f32
    const int*   pairs = (const int*)d_in[1];     // (65536, 2) i32
    const float* W1    = (const float*)d_in[2];   // (1024, 2048) f32
    const float* b1    = (const float*)d_in[3];   // (1024,) f32
    const float* W2    = (const float*)d_in[4];   // (8, 1024) f32
    const float* b2    = (const float*)d_in[5];   // (8,) f32
    float*       out   = (float*)d_out;           // (65536, 8) f32

    cudaLaunchAttribute attr[1];
    attr[0].id = cudaLaunchAttributeProgrammaticStreamSerialization;
    attr[0].val.programmaticStreamSerializationAllowed = 1;

    cudaLaunchConfig_t cfg = {};
    cfg.attrs    = attr;
    cfg.numAttrs = 1;
    cfg.stream   = 0;

    // m_kernel now also PDL: overlaps the previous graph replay's gather
    // drain (no data conflict; no internal sync needed).
    cfg.gridDim = dim3(128, 1, 1);  cfg.blockDim = dim3(256, 1, 1);
    cudaLaunchKernelEx(&cfg, m_kernel, W1, W2, b1, b2);

    cfg.gridDim = dim3(256, 1, 1);  cfg.blockDim = dim3(256, 1, 1);
    cudaLaunchKernelEx(&cfg, u_kernel, feats);

    cfg.gridDim = dim3(256, 1, 1);  cfg.blockDim = dim3(256, 1, 1);
    cudaLaunchKernelEx(&cfg, gather_kernel, pairs, (float*)d_out);
}